// round 7
// baseline (speedup 1.0000x reference)
#include <cuda_runtime.h>

// Segment mean: x[N,128] fp32, sorted segments, lengths[B], B<=16.
// out[b,d] = sum_{i in seg b} x[i,d] / lengths[b]
//
// SINGLE launch, last-block-done epilogue. g_sums/g_count are zero at module
// load; the epilogue restores them to zero so graph replay is deterministic.
//
// GRID = 4736 = 4 * (148 SMs * 8 CTAs/SM): four exactly-full waves; smaller
// CTAs average out the per-CTA completion spread (B300 multi-CTA spread) so
// the straggler tail shrinks. __launch_bounds__(256,8) pins regs <= 32.

#define NSEG_MAX 16
#define DIM 128
#define THREADS 256
#define GRID 4736

__device__ float        g_sums[NSEG_MAX * DIM];  // zero at module load
__device__ unsigned int g_count;                 // zero at module load

__global__ void __launch_bounds__(THREADS, 8)
gab_fused_kernel(const float4* __restrict__ x,
                 const int* __restrict__ len,
                 float* __restrict__ out,
                 int n_rows, int rows_per_block, int b, int total_out) {
    __shared__ int   s_offs[NSEG_MAX + 1];
    __shared__ float s_part[8][DIM];
    __shared__ bool  s_last;

    // Warp 0: inclusive shfl-scan of lengths -> offsets (b <= 16 <= 32).
    if (threadIdx.x < 32) {
        int v = (threadIdx.x < b) ? __ldg(len + threadIdx.x) : 0;
        #pragma unroll
        for (int d = 1; d < 32; d <<= 1) {
            int t = __shfl_up_sync(0xffffffff, v, d);
            if ((threadIdx.x & 31) >= d) v += t;
        }
        if (threadIdx.x == 0) s_offs[0] = 0;
        if (threadIdx.x < b) s_offs[threadIdx.x + 1] = v;
    }
    __syncthreads();

    const int start = blockIdx.x * rows_per_block;
    const int end   = min(start + rows_per_block, n_rows);

    const int tx = threadIdx.x & 31;   // float4 column 0..31
    const int ty = threadIdx.x >> 5;   // row lane 0..7

    if (start < end) {
        int s0 = 0;
        while (s0 + 1 < b && s_offs[s0 + 1] <= start) s0++;

        for (int s = s0; s < b && s_offs[s] < end; s++) {
            const int r0 = max(start, s_offs[s]);
            const int r1 = min(end,   s_offs[s + 1]);
            // [r0, r1) uniform across the block -> __syncthreads below is safe

            float4 a0 = make_float4(0.f, 0.f, 0.f, 0.f);
            float4 a1 = make_float4(0.f, 0.f, 0.f, 0.f);

            int row = r0 + ty;
            for (; row + 8 < r1; row += 16) {
                float4 v0 = __ldg(x + (size_t)row * 32 + tx);
                float4 v1 = __ldg(x + (size_t)(row + 8) * 32 + tx);
                a0.x += v0.x; a0.y += v0.y; a0.z += v0.z; a0.w += v0.w;
                a1.x += v1.x; a1.y += v1.y; a1.z += v1.z; a1.w += v1.w;
            }
            if (row < r1) {
                float4 v0 = __ldg(x + (size_t)row * 32 + tx);
                a0.x += v0.x; a0.y += v0.y; a0.z += v0.z; a0.w += v0.w;
            }
            a0.x += a1.x; a0.y += a1.y; a0.z += a1.z; a0.w += a1.w;

            s_part[ty][tx * 4 + 0] = a0.x;
            s_part[ty][tx * 4 + 1] = a0.y;
            s_part[ty][tx * 4 + 2] = a0.z;
            s_part[ty][tx * 4 + 3] = a0.w;
            __syncthreads();

            if (threadIdx.x < DIM) {
                float v = 0.f;
                #pragma unroll
                for (int w = 0; w < 8; w++) v += s_part[w][threadIdx.x];
                if (v != 0.0f) atomicAdd(&g_sums[s * DIM + threadIdx.x], v);
            }
            __syncthreads();
        }
    }

    // ---- last-block-done epilogue ----
    __threadfence();  // make this block's atomics visible before the ticket
    if (threadIdx.x == 0) {
        unsigned int old = atomicAdd(&g_count, 1u);
        s_last = (old == (unsigned int)(gridDim.x - 1));
    }
    __syncthreads();

    if (s_last) {
        __threadfence();  // acquire: order reads of g_sums after the ticket
        for (int i = threadIdx.x; i < total_out; i += THREADS) {
            float v = *((volatile float*)&g_sums[i]);
            out[i] = v / (float)__ldg(len + i / DIM);
            g_sums[i] = 0.0f;  // restore initial state for next replay
        }
        if (threadIdx.x == 0) g_count = 0u;
    }
}

// Generic fallback (unexpected shapes): straight global atomics, slow but correct.
__device__ float g_generic_sums[4096];
__global__ void gab_generic_kernel(const float* __restrict__ x,
                                   const int* __restrict__ seg,
                                   int n_rows, int d, float* __restrict__ sums) {
    long long i = (long long)blockIdx.x * blockDim.x + threadIdx.x;
    long long total = (long long)n_rows * d;
    if (i < total) {
        int row = (int)(i / d);
        int col = (int)(i - (long long)row * d);
        atomicAdd(&sums[seg[row] * d + col], x[i]);
    }
}
__global__ void gab_generic_zero(int total) {
    int i = blockIdx.x * blockDim.x + threadIdx.x;
    if (i < total) g_generic_sums[i] = 0.0f;
}
__global__ void gab_generic_div(const int* __restrict__ lengths,
                                float* __restrict__ out, int total, int d) {
    int i = blockIdx.x * blockDim.x + threadIdx.x;
    if (i < total) out[i] = g_generic_sums[i] / (float)lengths[i / d];
}

extern "C" void kernel_launch(void* const* d_in, const int* in_sizes, int n_in,
                              void* d_out, int out_size) {
    const float* x   = (const float*)d_in[0];
    const int*   seg = (const int*)d_in[1];
    const int*   len = (const int*)d_in[2];
    float*       out = (float*)d_out;

    const int n_rows = in_sizes[1];                 // N
    const int b      = in_sizes[2];                 // B
    const int d      = in_sizes[0] / n_rows;        // D

    if (d == DIM && b <= NSEG_MAX && out_size == b * DIM) {
        const int rows_per_block = (n_rows + GRID - 1) / GRID;
        gab_fused_kernel<<<GRID, THREADS>>>((const float4*)x, len, out,
                                            n_rows, rows_per_block, b, out_size);
    } else {
        gab_generic_zero<<<(out_size + 255) / 256, 256>>>(out_size);
        long long total = (long long)n_rows * d;
        int grid = (int)((total + 255) / 256);
        gab_generic_kernel<<<grid, 256>>>(x, seg, n_rows, d, g_generic_sums);
        gab_generic_div<<<(out_size + 255) / 256, 256>>>(len, out, out_size, d);
    }
}

// round 8
// speedup vs baseline: 1.0633x; 1.0633x over previous
#include <cuda_runtime.h>

// Segment mean: x[N,128] fp32, sorted segments, lengths[B], B<=16.
// out[b,d] = sum_{i in seg b} x[i,d] / lengths[b]
//
// SINGLE launch, last-block-done epilogue. g_sums/g_count are zero at module
// load; the epilogue restores them to zero so graph replay is deterministic.
//
// GRID = 2368 = 2 * (148 SMs * 8 CTAs/SM): measured-best operating point
// (two exactly-full waves). __launch_bounds__(256,8) pins regs <= 32.
// x is a pure 512MB stream with no reuse -> __ldcs (evict-first) keeps it
// from thrashing L2.

#define NSEG_MAX 16
#define DIM 128
#define THREADS 256
#define GRID 2368

__device__ float        g_sums[NSEG_MAX * DIM];  // zero at module load
__device__ unsigned int g_count;                 // zero at module load

__global__ void __launch_bounds__(THREADS, 8)
gab_fused_kernel(const float4* __restrict__ x,
                 const int* __restrict__ len,
                 float* __restrict__ out,
                 int n_rows, int rows_per_block, int b, int total_out) {
    __shared__ int   s_offs[NSEG_MAX + 1];
    __shared__ float s_part[8][DIM];
    __shared__ bool  s_last;

    // Warp 0: inclusive shfl-scan of lengths -> offsets (b <= 16 <= 32).
    if (threadIdx.x < 32) {
        int v = (threadIdx.x < b) ? __ldg(len + threadIdx.x) : 0;
        #pragma unroll
        for (int d = 1; d < 32; d <<= 1) {
            int t = __shfl_up_sync(0xffffffff, v, d);
            if ((threadIdx.x & 31) >= d) v += t;
        }
        if (threadIdx.x == 0) s_offs[0] = 0;
        if (threadIdx.x < b) s_offs[threadIdx.x + 1] = v;
    }
    __syncthreads();

    const int start = blockIdx.x * rows_per_block;
    const int end   = min(start + rows_per_block, n_rows);

    const int tx = threadIdx.x & 31;   // float4 column 0..31
    const int ty = threadIdx.x >> 5;   // row lane 0..7

    if (start < end) {
        int s0 = 0;
        while (s0 + 1 < b && s_offs[s0 + 1] <= start) s0++;

        for (int s = s0; s < b && s_offs[s] < end; s++) {
            const int r0 = max(start, s_offs[s]);
            const int r1 = min(end,   s_offs[s + 1]);
            // [r0, r1) uniform across the block -> __syncthreads below is safe

            float4 a0 = make_float4(0.f, 0.f, 0.f, 0.f);
            float4 a1 = make_float4(0.f, 0.f, 0.f, 0.f);

            int row = r0 + ty;
            for (; row + 8 < r1; row += 16) {
                float4 v0 = __ldcs(x + (size_t)row * 32 + tx);
                float4 v1 = __ldcs(x + (size_t)(row + 8) * 32 + tx);
                a0.x += v0.x; a0.y += v0.y; a0.z += v0.z; a0.w += v0.w;
                a1.x += v1.x; a1.y += v1.y; a1.z += v1.z; a1.w += v1.w;
            }
            if (row < r1) {
                float4 v0 = __ldcs(x + (size_t)row * 32 + tx);
                a0.x += v0.x; a0.y += v0.y; a0.z += v0.z; a0.w += v0.w;
            }
            a0.x += a1.x; a0.y += a1.y; a0.z += a1.z; a0.w += a1.w;

            s_part[ty][tx * 4 + 0] = a0.x;
            s_part[ty][tx * 4 + 1] = a0.y;
            s_part[ty][tx * 4 + 2] = a0.z;
            s_part[ty][tx * 4 + 3] = a0.w;
            __syncthreads();

            if (threadIdx.x < DIM) {
                float v = 0.f;
                #pragma unroll
                for (int w = 0; w < 8; w++) v += s_part[w][threadIdx.x];
                if (v != 0.0f) atomicAdd(&g_sums[s * DIM + threadIdx.x], v);
            }
            __syncthreads();
        }
    }

    // ---- last-block-done epilogue ----
    __threadfence();  // make this block's atomics visible before the ticket
    if (threadIdx.x == 0) {
        unsigned int old = atomicAdd(&g_count, 1u);
        s_last = (old == (unsigned int)(gridDim.x - 1));
    }
    __syncthreads();

    if (s_last) {
        __threadfence();  // acquire: order reads of g_sums after the ticket
        for (int i = threadIdx.x; i < total_out; i += THREADS) {
            float v = *((volatile float*)&g_sums[i]);
            out[i] = v / (float)__ldg(len + i / DIM);
            g_sums[i] = 0.0f;  // restore initial state for next replay
        }
        if (threadIdx.x == 0) g_count = 0u;
    }
}

// Generic fallback (unexpected shapes): straight global atomics, slow but correct.
__device__ float g_generic_sums[4096];
__global__ void gab_generic_kernel(const float* __restrict__ x,
                                   const int* __restrict__ seg,
                                   int n_rows, int d, float* __restrict__ sums) {
    long long i = (long long)blockIdx.x * blockDim.x + threadIdx.x;
    long long total = (long long)n_rows * d;
    if (i < total) {
        int row = (int)(i / d);
        int col = (int)(i - (long long)row * d);
        atomicAdd(&sums[seg[row] * d + col], x[i]);
    }
}
__global__ void gab_generic_zero(int total) {
    int i = blockIdx.x * blockDim.x + threadIdx.x;
    if (i < total) g_generic_sums[i] = 0.0f;
}
__global__ void gab_generic_div(const int* __restrict__ lengths,
                                float* __restrict__ out, int total, int d) {
    int i = blockIdx.x * blockDim.x + threadIdx.x;
    if (i < total) out[i] = g_generic_sums[i] / (float)lengths[i / d];
}

extern "C" void kernel_launch(void* const* d_in, const int* in_sizes, int n_in,
                              void* d_out, int out_size) {
    const float* x   = (const float*)d_in[0];
    const int*   seg = (const int*)d_in[1];
    const int*   len = (const int*)d_in[2];
    float*       out = (float*)d_out;

    const int n_rows = in_sizes[1];                 // N
    const int b      = in_sizes[2];                 // B
    const int d      = in_sizes[0] / n_rows;        // D

    if (d == DIM && b <= NSEG_MAX && out_size == b * DIM) {
        const int rows_per_block = (n_rows + GRID - 1) / GRID;
        gab_fused_kernel<<<GRID, THREADS>>>((const float4*)x, len, out,
                                            n_rows, rows_per_block, b, out_size);
    } else {
        gab_generic_zero<<<(out_size + 255) / 256, 256>>>(out_size);
        long long total = (long long)n_rows * d;
        int grid = (int)((total + 255) / 256);
        gab_generic_kernel<<<grid, 256>>>(x, seg, n_rows, d, g_generic_sums);
        gab_generic_div<<<(out_size + 255) / 256, 256>>>(len, out, out_size, d);
    }
}